// round 14
// baseline (speedup 1.0000x reference)
#include <cuda_runtime.h>
#include <cuda_fp16.h>
#include <cstdint>

// Problem constants (shapes fixed by the dataset)
#define B_   2
#define H_   128
#define W_   256
#define C_   256
#define NH_  8
#define D_   32
#define M_   (B_*H_*W_)            // 65536 rows
#define SCALE_ 0.17677669529663687f  // 32^-0.5
#define LOG2E_ 1.4426950408889634f

// Scratch (allocation-free rule: __device__ globals) — all fp16
__device__ __half g_xh[(size_t)M_*C_];
__device__ __half g_q [(size_t)M_*C_];   // h-axis qkv
__device__ __half g_k [(size_t)M_*C_];
__device__ __half g_v [(size_t)M_*C_];
__device__ __half g_q2[(size_t)M_*C_];   // w-axis qkv (independent chain)
__device__ __half g_k2[(size_t)M_*C_];
__device__ __half g_v2[(size_t)M_*C_];
__device__ __half g_oh[(size_t)M_*C_];
__device__ __half g_ow[(size_t)M_*C_];
// 8 half weight matrices, native [K][N] layout:
// 0 Wq_h(*SCALE*LOG2E) 1 Wk_h 2 Wv_h 3 Wq_w(*SCALE*LOG2E) 4 Wk_w 5 Wv_w 6 Wo_h 7 Wo_w
__device__ __half g_wh[(size_t)8*256*256];

// ---------------------------------------------------------------------------
// helpers
// ---------------------------------------------------------------------------
static __device__ __forceinline__ uint32_t smem_u32(const void* p) {
    uint32_t a;
    asm("{ .reg .u64 t; cvta.to.shared.u64 t, %1; cvt.u32.u64 %0, t; }"
        : "=r"(a) : "l"(p));
    return a;
}
static __device__ __forceinline__ uint32_t packh2(float lo, float hi) {
    __half2 h = __float22half2_rn(make_float2(lo, hi));
    return *(uint32_t*)&h;
}
// m16n8k16 fp16 mma (f32 accum), D accumulates in place
static __device__ __forceinline__ void mma16(float* d, const uint32_t* a, uint32_t b0, uint32_t b1) {
    asm volatile(
        "mma.sync.aligned.m16n8k16.row.col.f32.f16.f16.f32 "
        "{%0,%1,%2,%3}, {%4,%5,%6,%7}, {%8,%9}, {%0,%1,%2,%3};"
        : "+f"(d[0]), "+f"(d[1]), "+f"(d[2]), "+f"(d[3])
        : "r"(a[0]), "r"(a[1]), "r"(a[2]), "r"(a[3]), "r"(b0), "r"(b1));
}
#define LDSM4(R, ADDR) \
    asm volatile("ldmatrix.sync.aligned.m8n8.x4.shared.b16 {%0,%1,%2,%3}, [%4];" \
        : "=r"((R)[0]), "=r"((R)[1]), "=r"((R)[2]), "=r"((R)[3]) : "r"(ADDR))
#define LDSM4T(R, ADDR) \
    asm volatile("ldmatrix.sync.aligned.m8n8.x4.trans.shared.b16 {%0,%1,%2,%3}, [%4];" \
        : "=r"((R)[0]), "=r"((R)[1]), "=r"((R)[2]), "=r"((R)[3]) : "r"(ADDR))
#define LDSM2T(R, ADDR) \
    asm volatile("ldmatrix.sync.aligned.m8n8.x2.trans.shared.b16 {%0,%1}, [%2];" \
        : "=r"((R)[0]), "=r"((R)[1]) : "r"(ADDR))
#define EX2H2(r) asm("ex2.approx.f16x2 %0, %0;" : "+r"(r))

#define CP_ASYNC16(dst, src) \
    asm volatile("cp.async.ca.shared.global [%0], [%1], 16;" :: "r"(dst), "l"(src))
#define CP_COMMIT() asm volatile("cp.async.commit_group;" ::: "memory")
#define CP_WAIT1()  asm volatile("cp.async.wait_group 1;" ::: "memory")
#define CP_WAIT0()  asm volatile("cp.async.wait_group 0;" ::: "memory")

// ---------------------------------------------------------------------------
// Conversion prepasses: x -> half, weights -> half (SCALE*LOG2E into Wq)
// ---------------------------------------------------------------------------
__global__ __launch_bounds__(256) void conv_x(const float* __restrict__ x)
{
    const size_t i = ((size_t)blockIdx.x * 256 + threadIdx.x) * 8;
    float4 a = *(const float4*)(x + i);
    float4 b = *(const float4*)(x + i + 4);
    uint4 o;
    o.x = packh2(a.x, a.y); o.y = packh2(a.z, a.w);
    o.z = packh2(b.x, b.y); o.w = packh2(b.z, b.w);
    *(uint4*)(g_xh + i) = o;
}

__global__ __launch_bounds__(256) void conv_w(
    const float* w0, const float* w1, const float* w2, const float* w3,
    const float* w4, const float* w5, const float* w6, const float* w7)
{
    const float* ws[8] = {w0, w1, w2, w3, w4, w5, w6, w7};
    const size_t i = ((size_t)blockIdx.x * 256 + threadIdx.x) * 8;
    const int m = (int)(i >> 16);
    const size_t off = i & 65535;
    const float s = (m == 0 || m == 3) ? SCALE_ * LOG2E_ : 1.0f;
    const float* src = ws[m] + off;
    float4 a = *(const float4*)(src);
    float4 b = *(const float4*)(src + 4);
    uint4 o;
    o.x = packh2(a.x*s, a.y*s); o.y = packh2(a.z*s, a.w*s);
    o.z = packh2(b.x*s, b.y*s); o.w = packh2(b.z*s, b.w*s);
    *(uint4*)(g_wh + (size_t)m*65536 + off) = o;
}

// ---------------------------------------------------------------------------
// fp16 GEMM core, cp.async double-buffered K=64 chunks (2 CTAs/SM).
// C[128,128] = A[128,256] @ W[256,128-slice].
// 8 warps = (wm 0..3) x (wn 0..1), warp tile 32x64.
// smem/stage: A[128][72]h + B[64][136]h = 35,840 B; 2 stages = 71,680 B.
// ---------------------------------------------------------------------------
#define AP 72
#define BP 136
#define ABUF (128*AP)
#define BBUF (64*BP)
#define STG  (ABUF + BBUF)
#define GEMM_SMEM_BYTES (2*STG*2)   // 71,680 B

static __device__ __forceinline__ void gemm_issue(
    uint32_t uA, uint32_t uB,
    const __half* __restrict__ Agl, const __half* __restrict__ Wgl,
    int m0, int n0, int kc, int tid)
{
#pragma unroll
    for (int i = 0; i < 4; i++) {
        const int lin = tid + 256*i;
        const int ar = lin >> 3, ac = (lin & 7) * 8;
        CP_ASYNC16(uA + (ar*AP + ac)*2, Agl + (size_t)(m0+ar)*C_ + kc*64 + ac);
        const int br = lin >> 4, bc = (lin & 15) * 8;
        CP_ASYNC16(uB + (br*BP + bc)*2, Wgl + (size_t)(kc*64+br)*C_ + n0 + bc);
    }
    CP_COMMIT();
}

static __device__ __forceinline__ void gemm_compute(
    float acc[2][8][4], uint32_t uA, uint32_t uB,
    int wm, int wn, int lrow, int lcol8)
{
#pragma unroll
    for (int ks = 0; ks < 4; ks++) {
        uint32_t a[2][4];
#pragma unroll
        for (int ma = 0; ma < 2; ma++)
            LDSM4(a[ma], uA + ((wm*32 + ma*16 + lrow)*AP + ks*16 + lcol8)*2);
        uint32_t b[4][4];
#pragma unroll
        for (int nt = 0; nt < 4; nt++)
            LDSM4T(b[nt], uB + ((ks*16 + lrow)*BP + wn*64 + nt*16 + lcol8)*2);
#pragma unroll
        for (int ma = 0; ma < 2; ma++)
#pragma unroll
            for (int nt = 0; nt < 4; nt++) {
                mma16(acc[ma][2*nt  ], a[ma], b[nt][0], b[nt][1]);
                mma16(acc[ma][2*nt+1], a[ma], b[nt][2], b[nt][3]);
            }
    }
}

// shared 4-chunk pipelined GEMM body (K=256), acc left in registers
static __device__ __forceinline__ void gemm_body(
    float acc[2][8][4], const __half* __restrict__ Agl, const __half* __restrict__ Wgl,
    uint32_t u0, int m0, int n0, int tid, int wm, int wn, int lrow, int lcol8)
{
    const uint32_t uAb[2] = {u0, u0 + STG*2};
    const uint32_t uBb[2] = {u0 + ABUF*2, u0 + STG*2 + ABUF*2};

    gemm_issue(uAb[0], uBb[0], Agl, Wgl, m0, n0, 0, tid);
    gemm_issue(uAb[1], uBb[1], Agl, Wgl, m0, n0, 1, tid);

#pragma unroll 1
    for (int c = 0; c < 4; c++) {
        if (c < 3) { CP_WAIT1(); } else { CP_WAIT0(); }
        __syncthreads();
        gemm_compute(acc, uAb[c & 1], uBb[c & 1], wm, wn, lrow, lcol8);
        if (c < 2) {
            __syncthreads();   // all warps done reading this buffer
            gemm_issue(uAb[c & 1], uBb[c & 1], Agl, Wgl, m0, n0, c + 2, tid);
        }
    }
}

// fused QKV: grid (M/128, 2, 3); z selects weight matrix; wbase selects the
// weight set AND the destination buffers (device-side symbol resolution).
__global__ __launch_bounds__(256, 2) void qkv16(int wbase)
{
    extern __shared__ __half sh[];
    const uint32_t u0 = smem_u32(sh);
    const int tid = threadIdx.x, wid = tid >> 5, lane = tid & 31;
    const int g = lane >> 2, cc = lane & 3;
    const int lrow = (lane & 7) + ((lane >> 3) & 1) * 8;
    const int lcol8 = (lane >> 4) * 8;
    const int wm = wid & 3, wn = wid >> 2;
    const int m0 = blockIdx.x * 128, n0 = blockIdx.y * 128;
    const int z = blockIdx.z;
    const __half* Wgl = g_wh + (size_t)(wbase + z) * 65536;
    __half* Cg;
    if (wbase == 0) Cg = (z == 0) ? g_q  : (z == 1 ? g_k  : g_v );
    else            Cg = (z == 0) ? g_q2 : (z == 1 ? g_k2 : g_v2);

    float acc[2][8][4];
#pragma unroll
    for (int a = 0; a < 2; a++)
#pragma unroll
        for (int b = 0; b < 8; b++)
#pragma unroll
            for (int c = 0; c < 4; c++) acc[a][b][c] = 0.f;

    gemm_body(acc, g_xh, Wgl, u0, m0, n0, tid, wm, wn, lrow, lcol8);

#pragma unroll
    for (int ma = 0; ma < 2; ma++)
#pragma unroll
        for (int na = 0; na < 8; na++) {
            const int row = m0 + wm*32 + ma*16 + g;
            const int col = n0 + wn*64 + na*8 + 2*cc;
            *(uint32_t*)(Cg + (size_t)row*C_ + col)     = packh2(acc[ma][na][0], acc[ma][na][1]);
            *(uint32_t*)(Cg + (size_t)(row+8)*C_ + col) = packh2(acc[ma][na][2], acc[ma][na][3]);
        }
}

// output pass 1: Cout = OH@Wo_h + (bo_h + bo_w); grid (M/128, 2)
__global__ __launch_bounds__(256, 2) void out16_p1(
    const float* __restrict__ bo1, const float* __restrict__ bo2,
    float* __restrict__ Cout)
{
    extern __shared__ __half sh[];
    const uint32_t u0 = smem_u32(sh);
    const int tid = threadIdx.x, wid = tid >> 5, lane = tid & 31;
    const int g = lane >> 2, cc = lane & 3;
    const int lrow = (lane & 7) + ((lane >> 3) & 1) * 8;
    const int lcol8 = (lane >> 4) * 8;
    const int wm = wid & 3, wn = wid >> 2;
    const int m0 = blockIdx.x * 128, n0 = blockIdx.y * 128;

    float acc[2][8][4];
#pragma unroll
    for (int a = 0; a < 2; a++)
#pragma unroll
        for (int b = 0; b < 8; b++)
#pragma unroll
            for (int c = 0; c < 4; c++) acc[a][b][c] = 0.f;

    gemm_body(acc, g_oh, g_wh + (size_t)6*65536, u0, m0, n0, tid, wm, wn, lrow, lcol8);

#pragma unroll
    for (int ma = 0; ma < 2; ma++)
#pragma unroll
        for (int na = 0; na < 8; na++) {
            const int row = m0 + wm*32 + ma*16 + g;
            const int col = n0 + wn*64 + na*8 + 2*cc;
            const float b0 = bo1[col]   + bo2[col];
            const float b1 = bo1[col+1] + bo2[col+1];
            *(float2*)(Cout + (size_t)row*C_ + col) =
                make_float2(acc[ma][na][0] + b0, acc[ma][na][1] + b1);
            *(float2*)(Cout + (size_t)(row+8)*C_ + col) =
                make_float2(acc[ma][na][2] + b0, acc[ma][na][3] + b1);
        }
}

// output pass 2: Cout += OW@Wo_w (event-ordered after pass 1); grid (M/128, 2)
__global__ __launch_bounds__(256, 2) void out16_p2(float* __restrict__ Cout)
{
    extern __shared__ __half sh[];
    const uint32_t u0 = smem_u32(sh);
    const int tid = threadIdx.x, wid = tid >> 5, lane = tid & 31;
    const int g = lane >> 2, cc = lane & 3;
    const int lrow = (lane & 7) + ((lane >> 3) & 1) * 8;
    const int lcol8 = (lane >> 4) * 8;
    const int wm = wid & 3, wn = wid >> 2;
    const int m0 = blockIdx.x * 128, n0 = blockIdx.y * 128;

    float acc[2][8][4];
#pragma unroll
    for (int a = 0; a < 2; a++)
#pragma unroll
        for (int b = 0; b < 8; b++)
#pragma unroll
            for (int c = 0; c < 4; c++) acc[a][b][c] = 0.f;

    gemm_body(acc, g_ow, g_wh + (size_t)7*65536, u0, m0, n0, tid, wm, wn, lrow, lcol8);

#pragma unroll
    for (int ma = 0; ma < 2; ma++)
#pragma unroll
        for (int na = 0; na < 8; na++) {
            const int row = m0 + wm*32 + ma*16 + g;
            const int col = n0 + wn*64 + na*8 + 2*cc;
            float* p0 = Cout + (size_t)row*C_ + col;
            float* p1 = Cout + (size_t)(row+8)*C_ + col;
            float2 c0 = *(float2*)p0;
            float2 c1 = *(float2*)p1;
            *(float2*)p0 = make_float2(c0.x + acc[ma][na][0], c0.y + acc[ma][na][1]);
            *(float2*)p1 = make_float2(c1.x + acc[ma][na][2], c1.y + acc[ma][na][3]);
        }
}

// ---------------------------------------------------------------------------
// fp16 flash attention, m=2 warp tiles (unchanged from round 13)
// ---------------------------------------------------------------------------
#define ATTN_PAD 40
#define ATTN_SMEM2 (3*256*ATTN_PAD*2)   // 61,440 B (both kernels)

template<int L, int WPG>
static __device__ __forceinline__ void attn_m2(
    size_t base, int rstride,
    const __half* __restrict__ Qg, const __half* __restrict__ Kg,
    const __half* __restrict__ Vg, __half* __restrict__ Og,
    __half* smg, int tidg)
{
    constexpr int NT = WPG * 32;
    __half* Ks = smg;
    __half* Vs = smg + L*ATTN_PAD;
    __half* Qs = smg + 2*L*ATTN_PAD;
    const uint32_t uK = smem_u32(Ks), uV = smem_u32(Vs), uQ = smem_u32(Qs);

    const int lane = tidg & 31, wig = tidg >> 5;   // warp within group
    const int g = lane >> 2, cc = lane & 3;
    const int lrow = (lane & 7) + ((lane >> 3) & 1) * 8;
    const int lcol8 = (lane >> 4) * 8;

    // ---- load K,V,Q (L rows x 32 cols each = 4 uint4 iterations) ----
#pragma unroll
    for (int i = 0; i < 4; i++) {
        const int lin = tidg + NT*i;
        const int r = lin >> 2, cs = (lin & 3) * 8;
        *(uint4*)(Ks + r*ATTN_PAD + cs) = *(const uint4*)(Kg + base + (size_t)r*rstride + cs);
        *(uint4*)(Vs + r*ATTN_PAD + cs) = *(const uint4*)(Vg + base + (size_t)r*rstride + cs);
        *(uint4*)(Qs + r*ATTN_PAD + cs) = *(const uint4*)(Qg + base + (size_t)r*rstride + cs);
    }
    // V ones column at 32 (33..39 zero) for the rowsum mma
    for (int r = tidg; r < L; r += NT)
        *(uint4*)(Vs + r*ATTN_PAD + 32) = make_uint4(0x3C00u, 0u, 0u, 0u);
    __syncthreads();

    // Q fragments: 2 m-tiles x 2 k16 steps (d=32)
    uint32_t qf[2][2][4];
#pragma unroll
    for (int ma = 0; ma < 2; ma++)
#pragma unroll
        for (int ks = 0; ks < 2; ks++)
            LDSM4(qf[ma][ks], uQ + ((wig*32 + ma*16 + lrow)*ATTN_PAD + ks*16 + lcol8)*2);

    float o[2][5][4];   // [m-tile][4 d-tiles + ones(rowsum)][regs]
#pragma unroll
    for (int ma = 0; ma < 2; ma++)
#pragma unroll
        for (int nt = 0; nt < 5; nt++)
#pragma unroll
            for (int c = 0; c < 4; c++) o[ma][nt][c] = 0.f;

#pragma unroll 2
    for (int jc = 0; jc < L/16; jc++) {
        // K frags (B non-trans): (r0,r2)=jtile0, (r1,r3)=jtile1 — shared by both m-tiles
        uint32_t kf[2][4];
#pragma unroll
        for (int dd = 0; dd < 2; dd++)
            LDSM4(kf[dd], uK + ((jc*16 + lrow)*ATTN_PAD + dd*16 + lcol8)*2);
        // V frags (B trans) + ones column — shared by both m-tiles
        uint32_t vf[2][4], vo[2];
#pragma unroll
        for (int dd = 0; dd < 2; dd++)
            LDSM4T(vf[dd], uV + ((jc*16 + lrow)*ATTN_PAD + dd*16 + lcol8)*2);
        LDSM2T(vo, uV + ((jc*16 + (lane & 15))*ATTN_PAD + 32)*2);

#pragma unroll
        for (int ma = 0; ma < 2; ma++) {
            float sc[2][4];
#pragma unroll
            for (int n = 0; n < 2; n++)
#pragma unroll
                for (int c = 0; c < 4; c++) sc[n][c] = 0.f;
            mma16(sc[0], qf[ma][0], kf[0][0], kf[0][2]);
            mma16(sc[0], qf[ma][1], kf[1][0], kf[1][2]);
            mma16(sc[1], qf[ma][0], kf[0][1], kf[0][3]);
            mma16(sc[1], qf[ma][1], kf[1][1], kf[1][3]);

            // P = 2^S: pack to half2 (A-fragment layout), one ex2 per pair
            uint32_t aa[4];
            aa[0] = packh2(sc[0][0], sc[0][1]);   // row g,   jtile0
            aa[1] = packh2(sc[0][2], sc[0][3]);   // row g+8, jtile0
            aa[2] = packh2(sc[1][0], sc[1][1]);   // row g,   jtile1
            aa[3] = packh2(sc[1][2], sc[1][3]);   // row g+8, jtile1
            EX2H2(aa[0]); EX2H2(aa[1]); EX2H2(aa[2]); EX2H2(aa[3]);

            mma16(o[ma][0], aa, vf[0][0], vf[0][1]);
            mma16(o[ma][1], aa, vf[0][2], vf[0][3]);
            mma16(o[ma][2], aa, vf[1][0], vf[1][1]);
            mma16(o[ma][3], aa, vf[1][2], vf[1][3]);
            mma16(o[ma][4], aa, vo[0], vo[1]);
        }
    }

    // ---- finalize: rowsum in col 32 (cc==0 lane of quad) -> broadcast ----
#pragma unroll
    for (int ma = 0; ma < 2; ma++) {
        const float l0 = __shfl_sync(0xffffffffu, o[ma][4][0], lane & 28);
        const float l1 = __shfl_sync(0xffffffffu, o[ma][4][2], lane & 28);
        const float i0 = 1.0f / l0, i1 = 1.0f / l1;
        const int qr = wig*32 + ma*16 + g;
        __half* p0 = Og + base + (size_t)qr*rstride + 2*cc;
        __half* p1 = Og + base + (size_t)(qr+8)*rstride + 2*cc;
#pragma unroll
        for (int nt = 0; nt < 4; nt++) {
            *(uint32_t*)(p0 + nt*8) = packh2(o[ma][nt][0]*i0, o[ma][nt][1]*i0);
            *(uint32_t*)(p1 + nt*8) = packh2(o[ma][nt][2]*i1, o[ma][nt][3]*i1);
        }
    }
}

// height axis: 2 heads per CTA (groups of 128 threads); grid = B*W*NH/2
__global__ __launch_bounds__(256) void attn_h16()
{
    extern __shared__ __half sh[];
    const int tid = threadIdx.x;
    const int group = tid >> 7, tidg = tid & 127;
    const int idx = blockIdx.x * 2 + group;
    const int head = idx & 7;
    const int bw = idx >> 3;
    const int w = bw & (W_-1);
    const int b = bw >> 8;
    const size_t base = ((size_t)b*H_*W_ + w)*C_ + head*D_;
    attn_m2<128, 4>(base, W_*C_, g_q, g_k, g_v, g_oh,
                    sh + group * (3*128*ATTN_PAD), tidg);
}

// width axis: one CTA per (b, h, head); 8 warps x 32 rows = 256 = L
__global__ __launch_bounds__(256) void attn_w16()
{
    extern __shared__ __half sh[];
    const int idx = blockIdx.x;
    const int head = idx & 7;
    const int bh = idx >> 3;
    const int h = bh & (H_-1);
    const int b = bh >> 7;
    const size_t base = ((size_t)b*H_*W_ + (size_t)h*W_)*C_ + head*D_;
    attn_m2<256, 8>(base, C_, g_q2, g_k2, g_v2, g_ow, sh, threadIdx.x);
}

// ---------------------------------------------------------------------------
// Streams/events for DAG parallelism (host-side resources only, module-load).
// ---------------------------------------------------------------------------
static cudaStream_t s_str1, s_str2;
static cudaEvent_t  s_evF, s_evW, s_evQH, s_evA;
static struct _StrInit {
    _StrInit() {
        cudaStreamCreateWithFlags(&s_str1, cudaStreamNonBlocking);
        cudaStreamCreateWithFlags(&s_str2, cudaStreamNonBlocking);
        cudaEventCreateWithFlags(&s_evF,  cudaEventDisableTiming);
        cudaEventCreateWithFlags(&s_evW,  cudaEventDisableTiming);
        cudaEventCreateWithFlags(&s_evQH, cudaEventDisableTiming);
        cudaEventCreateWithFlags(&s_evA,  cudaEventDisableTiming);
    }
} s_strinit;

extern "C" void kernel_launch(void* const* d_in, const int* in_sizes, int n_in,
                              void* d_out, int out_size)
{
    const float* x    = (const float*)d_in[0];
    const float* Wq_h = (const float*)d_in[1];
    const float* Wk_h = (const float*)d_in[2];
    const float* Wv_h = (const float*)d_in[3];
    const float* Wo_h = (const float*)d_in[4];
    const float* bo_h = (const float*)d_in[5];
    const float* Wq_w = (const float*)d_in[6];
    const float* Wk_w = (const float*)d_in[7];
    const float* Wv_w = (const float*)d_in[8];
    const float* Wo_w = (const float*)d_in[9];
    const float* bo_w = (const float*)d_in[10];
    float* out = (float*)d_out;

    cudaFuncSetAttribute(qkv16,    cudaFuncAttributeMaxDynamicSharedMemorySize, GEMM_SMEM_BYTES);
    cudaFuncSetAttribute(out16_p1, cudaFuncAttributeMaxDynamicSharedMemorySize, GEMM_SMEM_BYTES);
    cudaFuncSetAttribute(out16_p2, cudaFuncAttributeMaxDynamicSharedMemorySize, GEMM_SMEM_BYTES);
    cudaFuncSetAttribute(attn_h16, cudaFuncAttributeMaxDynamicSharedMemorySize, ATTN_SMEM2);
    cudaFuncSetAttribute(attn_w16, cudaFuncAttributeMaxDynamicSharedMemorySize, ATTN_SMEM2);

    const dim3 qkv_grid(M_/128, C_/128, 3);
    const dim3 out_grid(M_/128, C_/128);

    // ---- fork: conv_w on s1, everything else rooted on default ----
    cudaEventRecord(s_evF, 0);
    cudaStreamWaitEvent(s_str1, s_evF, 0);

    conv_x<<<(M_*C_)/(256*8), 256>>>(x);
    conv_w<<<(8*256*256)/(256*8), 256, 0, s_str1>>>(
        Wq_h, Wk_h, Wv_h, Wq_w, Wk_w, Wv_w, Wo_h, Wo_w);
    cudaEventRecord(s_evW, s_str1);

    // ---- h-axis qkv first (serialized GEMMs; attention overlaps later) ----
    cudaStreamWaitEvent(0, s_evW, 0);
    qkv16<<<qkv_grid, 256, GEMM_SMEM_BYTES>>>(0);
    cudaEventRecord(s_evQH, 0);

    // ---- w-axis chain on s2: qkv_w overlaps attn_h; attn_w overlaps out1 ----
    cudaStreamWaitEvent(s_str2, s_evQH, 0);
    qkv16<<<qkv_grid, 256, GEMM_SMEM_BYTES, s_str2>>>(3);
    attn_w16<<<B_*H_*NH_, 256, ATTN_SMEM2, s_str2>>>();
    cudaEventRecord(s_evA, s_str2);

    // ---- default: attn_h, then out pass 1 (OH@Wo_h + biases) ----
    attn_h16<<<B_*W_*NH_/2, 256, ATTN_SMEM2>>>();
    out16_p1<<<out_grid, 256, GEMM_SMEM_BYTES>>>(bo_h, bo_w, out);

    // ---- join, then out pass 2 (+= OW@Wo_w) ----
    cudaStreamWaitEvent(0, s_evA, 0);
    out16_p2<<<out_grid, 256, GEMM_SMEM_BYTES>>>(out);
}